// round 2
// baseline (speedup 1.0000x reference)
#include <cuda_runtime.h>

#define TT  2048
#define CC  1024
#define NH  16
#define HS  64
#define BB  2
#define NHC (NH * CC)   // 16384

// Scratch (static device arrays; no allocation anywhere)
__device__ float g_attn[(size_t)BB * NH * TT * TT];  // [b,h,t,t]  512 MB
__device__ float g_o[(size_t)BB * TT * NHC];         // [b,t,h*C]  256 MB

// ---------------------------------------------------------------------------
// Kernel 1: S[b,h,m,n] = (1/8) * sum_k x[b,m,h*64+k] * x[b,n,h*64+k]
// 64x64 output tile per block, K=64 fully resident in smem.
// ---------------------------------------------------------------------------
__global__ __launch_bounds__(256) void scores_kernel(const float* __restrict__ x) {
    const int bh = blockIdx.z;
    const int b  = bh >> 4;
    const int h  = bh & 15;
    const float* xb = x + (size_t)b * TT * CC + h * HS;
    float* Sbh = g_attn + (size_t)bh * TT * TT;

    __shared__ float Qs[64][65];   // [m][k], pre-scaled by 1/8
    __shared__ float Kt[64][65];   // [k][n] (transposed)

    const int m0 = blockIdx.y * 64;
    const int n0 = blockIdx.x * 64;
    const int tid = threadIdx.x;
    const int lk = (tid & 15) * 4;   // k group
    const int lr = tid >> 4;         // row 0..15

    #pragma unroll
    for (int r = 0; r < 64; r += 16) {
        float4 q = *(const float4*)&xb[(size_t)(m0 + lr + r) * CC + lk];
        Qs[lr + r][lk + 0] = q.x * 0.125f;
        Qs[lr + r][lk + 1] = q.y * 0.125f;
        Qs[lr + r][lk + 2] = q.z * 0.125f;
        Qs[lr + r][lk + 3] = q.w * 0.125f;
        float4 kv = *(const float4*)&xb[(size_t)(n0 + lr + r) * CC + lk];
        Kt[lk + 0][lr + r] = kv.x;
        Kt[lk + 1][lr + r] = kv.y;
        Kt[lk + 2][lr + r] = kv.z;
        Kt[lk + 3][lr + r] = kv.w;
    }
    __syncthreads();

    const int tr = (tid >> 4) * 4;
    const int tc = (tid & 15) * 4;
    float acc[4][4] = {};

    #pragma unroll 16
    for (int k = 0; k < 64; k++) {
        float qm[4], kn[4];
        #pragma unroll
        for (int i = 0; i < 4; i++) qm[i] = Qs[tr + i][k];
        #pragma unroll
        for (int j = 0; j < 4; j++) kn[j] = Kt[k][tc + j];
        #pragma unroll
        for (int i = 0; i < 4; i++)
            #pragma unroll
            for (int j = 0; j < 4; j++)
                acc[i][j] += qm[i] * kn[j];
    }

    #pragma unroll
    for (int i = 0; i < 4; i++) {
        float4 o = make_float4(acc[i][0], acc[i][1], acc[i][2], acc[i][3]);
        *(float4*)&Sbh[(size_t)(m0 + tr + i) * TT + n0 + tc] = o;
    }
}

// ---------------------------------------------------------------------------
// Kernel 2: row softmax over last dim (2048). One block (256 thr) per row.
// ---------------------------------------------------------------------------
__global__ __launch_bounds__(256) void softmax_kernel() {
    float* p = g_attn + (size_t)blockIdx.x * TT;
    const int tid = threadIdx.x;
    __shared__ float red[8];

    float v[8];
    float mx = -1e30f;
    #pragma unroll
    for (int i = 0; i < 8; i++) {
        v[i] = p[tid + i * 256];
        mx = fmaxf(mx, v[i]);
    }
    #pragma unroll
    for (int o = 16; o; o >>= 1) mx = fmaxf(mx, __shfl_xor_sync(0xFFFFFFFFu, mx, o));
    if ((tid & 31) == 0) red[tid >> 5] = mx;
    __syncthreads();
    mx = red[0];
    #pragma unroll
    for (int i = 1; i < 8; i++) mx = fmaxf(mx, red[i]);
    __syncthreads();

    float sum = 0.f;
    #pragma unroll
    for (int i = 0; i < 8; i++) {
        v[i] = expf(v[i] - mx);
        sum += v[i];
    }
    #pragma unroll
    for (int o = 16; o; o >>= 1) sum += __shfl_xor_sync(0xFFFFFFFFu, sum, o);
    if ((tid & 31) == 0) red[tid >> 5] = sum;
    __syncthreads();
    sum = 0.f;
    #pragma unroll
    for (int i = 0; i < 8; i++) sum += red[i];
    const float inv = 1.0f / sum;

    #pragma unroll
    for (int i = 0; i < 8; i++) p[tid + i * 256] = v[i] * inv;
}

// ---------------------------------------------------------------------------
// Generic 128x128x16 register-tiled SGEMM tile (256 threads, 8x8 per thread).
// All dims assumed multiples of the tile (true for all call sites).
// ---------------------------------------------------------------------------
__device__ __forceinline__ void sgemm_tile(
    const float* __restrict__ A, int lda,
    const float* __restrict__ B, int ldb,
    float* __restrict__ C, int ldc,
    int K, int m0, int n0)
{
    __shared__ float As[16][132];  // [k][m] transposed, padded
    __shared__ float Bs[16][128];  // [k][n]

    const int tid  = threadIdx.x;
    const int aRow = tid >> 2;          // 0..63
    const int aCol = (tid & 3) * 4;     // 0,4,8,12
    const int bRow = tid >> 5;          // 0..7
    const int bCol = (tid & 31) * 4;    // 0..124
    const int trow = (tid >> 4) * 8;
    const int tcol = (tid & 15) * 8;

    float acc[8][8] = {};

    for (int k0 = 0; k0 < K; k0 += 16) {
        #pragma unroll
        for (int it = 0; it < 2; it++) {
            const int m = aRow + it * 64;
            float4 a = *(const float4*)&A[(size_t)(m0 + m) * lda + k0 + aCol];
            As[aCol + 0][m] = a.x;
            As[aCol + 1][m] = a.y;
            As[aCol + 2][m] = a.z;
            As[aCol + 3][m] = a.w;
            const int kk = bRow + it * 8;
            *(float4*)&Bs[kk][bCol] =
                *(const float4*)&B[(size_t)(k0 + kk) * ldb + n0 + bCol];
        }
        __syncthreads();

        #pragma unroll
        for (int k = 0; k < 16; k++) {
            float ra[8], rb[8];
            *(float4*)&ra[0] = *(const float4*)&As[k][trow];
            *(float4*)&ra[4] = *(const float4*)&As[k][trow + 4];
            *(float4*)&rb[0] = *(const float4*)&Bs[k][tcol];
            *(float4*)&rb[4] = *(const float4*)&Bs[k][tcol + 4];
            #pragma unroll
            for (int i = 0; i < 8; i++)
                #pragma unroll
                for (int j = 0; j < 8; j++)
                    acc[i][j] += ra[i] * rb[j];
        }
        __syncthreads();
    }

    #pragma unroll
    for (int i = 0; i < 8; i++) {
        float4 c0 = make_float4(acc[i][0], acc[i][1], acc[i][2], acc[i][3]);
        float4 c1 = make_float4(acc[i][4], acc[i][5], acc[i][6], acc[i][7]);
        float* cp = &C[(size_t)(m0 + trow + i) * ldc + n0 + tcol];
        *(float4*)&cp[0] = c0;
        *(float4*)&cp[4] = c1;
    }
}

// Kernel 3: O[b, t, h*C + c] = sum_s P[b,h,t,s] * x[b,s,c]
__global__ __launch_bounds__(256) void pv_kernel(const float* __restrict__ x) {
    const int bh = blockIdx.z;
    const int b  = bh >> 4;
    const int h  = bh & 15;
    const float* A  = g_attn + (size_t)bh * TT * TT;
    const float* Bp = x + (size_t)b * TT * CC;
    float* Cp = g_o + (size_t)b * TT * NHC + h * CC;
    sgemm_tile(A, TT, Bp, CC, Cp, NHC, TT, blockIdx.y * 128, blockIdx.x * 128);
}

// Kernel 4: out[b*t, :] = O_flat[b*t, 16384] @ W[16384, 1024]
__global__ __launch_bounds__(256) void proj_kernel(const float* __restrict__ w,
                                                   float* __restrict__ out) {
    sgemm_tile(g_o, NHC, w, CC, out, CC, NHC, blockIdx.y * 128, blockIdx.x * 128);
}

// ---------------------------------------------------------------------------
extern "C" void kernel_launch(void* const* d_in, const int* in_sizes, int n_in,
                              void* d_out, int out_size) {
    const float* x = (const float*)d_in[0];
    const float* w = (const float*)d_in[1];
    float* out = (float*)d_out;

    scores_kernel<<<dim3(TT / 64, TT / 64, BB * NH), 256>>>(x);
    softmax_kernel<<<BB * NH * TT, 256>>>();
    pv_kernel<<<dim3(CC / 128, TT / 128, BB * NH), 256>>>(x);
    proj_kernel<<<dim3(CC / 128, (BB * TT) / 128, 1), 256>>>(w, out);
}

// round 7
// speedup vs baseline: 4.0771x; 4.0771x over previous
#include <cuda_runtime.h>
#include <cstdint>

#define TT 2048
#define CC 1024
#define NH 16
#define BB 2
#define NHC (NH*CC)   // 16384

// ---- static device scratch (no allocation anywhere) ----
__device__ float g_attn[(size_t)BB*NH*TT*TT];  // 512 MB  scores / P
__device__ float g_o[(size_t)BB*TT*NHC];       // 256 MB  PV output
__device__ float g_xr[(size_t)BB*TT*CC];       // 16 MB   tf32-rounded x
__device__ float g_xT[(size_t)BB*CC*TT];       // 16 MB   x transposed [b,c,t]
__device__ float g_wT[(size_t)CC*NHC];         // 64 MB   W transposed [n,k]

// ---------------------------------------------------------------------------
// helpers (family-wide PTX only: cp.async / ldmatrix / mma.sync)
// ---------------------------------------------------------------------------
__device__ __forceinline__ float rn_tf32(float a){
    uint32_t u; asm("cvt.rna.tf32.f32 %0, %1;" : "=r"(u) : "f"(a));
    return __uint_as_float(u);
}
__device__ __forceinline__ uint32_t smem_u32(const void* p){
    uint32_t a;
    asm("{ .reg .u64 t; cvta.to.shared.u64 t, %1; cvt.u32.u64 %0, t; }"
        : "=r"(a) : "l"(p));
    return a;
}

#define CPA(dst,src) \
    asm volatile("cp.async.cg.shared.global [%0], [%1], 16;" :: "r"(dst), "l"(src))
#define CPA_COMMIT() asm volatile("cp.async.commit_group;" ::: "memory")
#define CPA_WAIT(n)  asm volatile("cp.async.wait_group %0;" :: "n"(n) : "memory")

__device__ __forceinline__ void ldm_x4(uint32_t* r, uint32_t a){
    asm volatile("ldmatrix.sync.aligned.m8n8.x4.shared.b16 {%0,%1,%2,%3}, [%4];"
        : "=r"(r[0]), "=r"(r[1]), "=r"(r[2]), "=r"(r[3]) : "r"(a));
}
__device__ __forceinline__ void mma8(float* c, const uint32_t* a, const uint32_t* b){
    asm volatile("mma.sync.aligned.m16n8k8.row.col.f32.tf32.tf32.f32 "
        "{%0,%1,%2,%3}, {%4,%5,%6,%7}, {%8,%9}, {%0,%1,%2,%3};"
        : "+f"(c[0]), "+f"(c[1]), "+f"(c[2]), "+f"(c[3])
        : "r"(a[0]), "r"(a[1]), "r"(a[2]), "r"(a[3]), "r"(b[0]), "r"(b[1]));
}

// ---------------------------------------------------------------------------
// Warp-MMA tf32 GEMM: C tile 128x128 per CTA, BK=32, 3-stage cp.async pipeline.
// A: K-major [m][k] (lda).  Bt: K-major transposed-B [n][k] (ldb).
// MODE: 0 = plain store, 1 = tf32-round store, 2 = scale store.
// smem: 3 stages x (A 16KB + B 16KB) = 96KB, 128B/row with XOR-16B swizzle.
// ---------------------------------------------------------------------------
template<int MODE>
__device__ __forceinline__ void gemm_ws(
    const float* __restrict__ A,  int lda,
    const float* __restrict__ Bt, int ldb,
    float* __restrict__ C, int ldc,
    int K, int m0, int n0, float scl)
{
    extern __shared__ char sm[];
    const uint32_t sb = smem_u32(sm);
    const int tid = threadIdx.x, lane = tid & 31, wid = tid >> 5;
    const int wm = (wid & 1) * 64;      // warp grid 2 (M) x 4 (N)
    const int wn = (wid >> 1) * 32;

    // gmem->smem copy assignment: 32 rows/pass, 8x16B chunks per 128B row
    const int lrow = tid >> 3, lcb = (tid & 7) * 16;
    const float* aptr = A  + (size_t)(m0 + lrow) * lda + (tid & 7) * 4;
    const float* bptr = Bt + (size_t)(n0 + lrow) * ldb + (tid & 7) * 4;

    auto load_stage = [&](int stg, int k0){
        const uint32_t base = sb + stg * 32768;
        #pragma unroll
        for (int i = 0; i < 4; i++){
            const int r = lrow + 32 * i;
            const uint32_t d = base + r * 128 + (lcb ^ ((r & 7) << 4));
            CPA(d,         aptr + (size_t)(32 * i) * lda + k0);
            CPA(d + 16384, bptr + (size_t)(32 * i) * ldb + k0);
        }
        CPA_COMMIT();
    };

    // ldmatrix per-lane row geometry
    const int arow = ((lane >> 3) & 1) * 8 + (lane & 7);   // A x4: sub0/2 rows 0-7, sub1/3 rows 8-15
    const int acb  = ((lane >> 4) & 1) * 16;               // k half (+4 tf32)
    const int bnr  = ((lane >> 4) & 1) * 8 + (lane & 7);   // B x4: nf pair rows
    const int bcb  = ((lane >> 3) & 1) * 16;               // k half

    uint32_t arb[4], arx[4], brb[2], brx[2];
    #pragma unroll
    for (int mf = 0; mf < 4; mf++){
        const int r = wm + mf * 16 + arow;
        arb[mf] = r * 128; arx[mf] = (r & 7) << 4;
    }
    #pragma unroll
    for (int p = 0; p < 2; p++){
        const int r = wn + p * 16 + bnr;
        brb[p] = r * 128; brx[p] = (r & 7) << 4;
    }

    const int S = K >> 5;
    load_stage(0, 0);
    load_stage(1, 32);

    float acc[4][4][4] = {};

    for (int s = 0; s < S; s++){
        if (s + 2 <= S) { CPA_WAIT(1); } else { CPA_WAIT(0); }
        __syncthreads();
        if (s + 2 < S) load_stage((s + 2) % 3, (s + 2) << 5);

        const uint32_t base = sb + (s % 3) * 32768;
        #pragma unroll
        for (int c = 0; c < 4; c++){               // 4 k-steps of 8 within BK=32
            uint32_t af[4][4], bf[2][4];
            #pragma unroll
            for (int mf = 0; mf < 4; mf++)
                ldm_x4(af[mf], base + arb[mf] + ((c * 32 + acb) ^ arx[mf]));
            #pragma unroll
            for (int p = 0; p < 2; p++)
                ldm_x4(bf[p], base + 16384 + brb[p] + ((c * 32 + bcb) ^ brx[p]));
            #pragma unroll
            for (int mf = 0; mf < 4; mf++)
                #pragma unroll
                for (int nf = 0; nf < 4; nf++)
                    mma8(acc[mf][nf], af[mf], &bf[nf >> 1][(nf & 1) * 2]);
        }
    }

    // epilogue: regs -> gmem
    const int lr = lane >> 2, lc = (lane & 3) * 2;
    #pragma unroll
    for (int mf = 0; mf < 4; mf++){
        const int row = m0 + wm + mf * 16 + lr;
        #pragma unroll
        for (int nf = 0; nf < 4; nf++){
            const int col = n0 + wn + nf * 8 + lc;
            float v0 = acc[mf][nf][0], v1 = acc[mf][nf][1];
            float v2 = acc[mf][nf][2], v3 = acc[mf][nf][3];
            if (MODE == 1){ v0 = rn_tf32(v0); v1 = rn_tf32(v1);
                            v2 = rn_tf32(v2); v3 = rn_tf32(v3); }
            if (MODE == 2){ v0 *= scl; v1 *= scl; v2 *= scl; v3 *= scl; }
            *(float2*)&C[(size_t)row * ldc + col]       = make_float2(v0, v1);
            *(float2*)&C[(size_t)(row + 8) * ldc + col] = make_float2(v2, v3);
        }
    }
}

// ---------------------------------------------------------------------------
// GEMM kernels
// ---------------------------------------------------------------------------
__global__ __launch_bounds__(256) void scores_mma(){
    const int bh = blockIdx.z, b = bh >> 4, h = bh & 15;
    const float* Ax = g_xr + (size_t)b * TT * CC + h * 64;
    gemm_ws<2>(Ax, CC, Ax, CC,
               g_attn + (size_t)bh * TT * TT, TT,
               64, blockIdx.y * 128, blockIdx.x * 128, 0.125f);
}

__global__ __launch_bounds__(256) void pv_mma(){
    const int bh = blockIdx.z, b = bh >> 4, h = bh & 15;
    gemm_ws<1>(g_attn + (size_t)bh * TT * TT, TT,
               g_xT + (size_t)b * CC * TT, TT,
               g_o + (size_t)b * TT * NHC + h * CC, NHC,
               TT, blockIdx.y * 128, blockIdx.x * 128, 0.f);
}

__global__ __launch_bounds__(256) void proj_mma(float* __restrict__ out){
    gemm_ws<0>(g_o, NHC, g_wT, NHC, out, CC,
               NHC, blockIdx.y * 128, blockIdx.x * 128, 0.f);
}

// ---------------------------------------------------------------------------
// Prep: round x to tf32 (g_xr) + transpose (g_xT); transpose+round W (g_wT)
// ---------------------------------------------------------------------------
__global__ __launch_bounds__(256) void prep_x(const float* __restrict__ x){
    __shared__ float t[32][33];
    const int b = blockIdx.z;
    const int t0 = blockIdx.x * 32, c0 = blockIdx.y * 32;
    const int tx = threadIdx.x & 31, ty = threadIdx.x >> 5;
    #pragma unroll
    for (int i = 0; i < 4; i++){
        const int row = ty + 8 * i;
        const size_t idx = (size_t)b * TT * CC + (size_t)(t0 + row) * CC + c0 + tx;
        float v = rn_tf32(x[idx]);
        g_xr[idx] = v;
        t[row][tx] = v;
    }
    __syncthreads();
    #pragma unroll
    for (int i = 0; i < 4; i++){
        const int row = ty + 8 * i;   // c index within tile
        g_xT[(size_t)b * CC * TT + (size_t)(c0 + row) * TT + t0 + tx] = t[tx][row];
    }
}

__global__ __launch_bounds__(256) void prep_w(const float* __restrict__ w){
    __shared__ float t[32][33];
    const int k0 = blockIdx.x * 32, n0 = blockIdx.y * 32;
    const int tx = threadIdx.x & 31, ty = threadIdx.x >> 5;
    #pragma unroll
    for (int i = 0; i < 4; i++){
        const int row = ty + 8 * i;
        t[row][tx] = rn_tf32(w[(size_t)(k0 + row) * CC + n0 + tx]);
    }
    __syncthreads();
    #pragma unroll
    for (int i = 0; i < 4; i++){
        const int row = ty + 8 * i;   // n index within tile
        g_wT[(size_t)(n0 + row) * NHC + k0 + tx] = t[tx][row];
    }
}

// ---------------------------------------------------------------------------
// Softmax over last dim (2048); writes tf32-rounded P in place.
// ---------------------------------------------------------------------------
__global__ __launch_bounds__(256) void softmax_kernel(){
    float* p = g_attn + (size_t)blockIdx.x * TT;
    const int tid = threadIdx.x;
    __shared__ float red[8];

    float v[8];
    float mx = -1e30f;
    #pragma unroll
    for (int i = 0; i < 8; i++){ v[i] = p[tid + i * 256]; mx = fmaxf(mx, v[i]); }
    #pragma unroll
    for (int o = 16; o; o >>= 1) mx = fmaxf(mx, __shfl_xor_sync(0xFFFFFFFFu, mx, o));
    if ((tid & 31) == 0) red[tid >> 5] = mx;
    __syncthreads();
    mx = red[0];
    #pragma unroll
    for (int i = 1; i < 8; i++) mx = fmaxf(mx, red[i]);
    __syncthreads();

    float sum = 0.f;
    #pragma unroll
    for (int i = 0; i < 8; i++){ v[i] = __expf(v[i] - mx); sum += v[i]; }
    #pragma unroll
    for (int o = 16; o; o >>= 1) sum += __shfl_xor_sync(0xFFFFFFFFu, sum, o);
    if ((tid & 31) == 0) red[tid >> 5] = sum;
    __syncthreads();
    sum = 0.f;
    #pragma unroll
    for (int i = 0; i < 8; i++) sum += red[i];
    const float inv = 1.0f / sum;

    #pragma unroll
    for (int i = 0; i < 8; i++) p[tid + i * 256] = rn_tf32(v[i] * inv);
}

// ---------------------------------------------------------------------------
extern "C" void kernel_launch(void* const* d_in, const int* in_sizes, int n_in,
                              void* d_out, int out_size) {
    const float* x = (const float*)d_in[0];
    const float* w = (const float*)d_in[1];
    float* out = (float*)d_out;

    const int SMEM = 3 * 32768;   // 98304
    cudaFuncSetAttribute(scores_mma, cudaFuncAttributeMaxDynamicSharedMemorySize, SMEM);
    cudaFuncSetAttribute(pv_mma,     cudaFuncAttributeMaxDynamicSharedMemorySize, SMEM);
    cudaFuncSetAttribute(proj_mma,   cudaFuncAttributeMaxDynamicSharedMemorySize, SMEM);

    prep_x<<<dim3(TT/32, CC/32, BB), 256>>>(x);
    prep_w<<<dim3(NHC/32, CC/32), 256>>>(w);
    scores_mma<<<dim3(TT/128, TT/128, BB*NH), 256, SMEM>>>();
    softmax_kernel<<<BB*NH*TT, 256>>>();
    pv_mma<<<dim3(CC/128, TT/128, BB*NH), 256, SMEM>>>();
    proj_mma<<<dim3(CC/128, (BB*TT)/128), 256, SMEM>>>(out);
}

// round 8
// speedup vs baseline: 7.4085x; 1.8171x over previous
#include <cuda_runtime.h>
#include <cuda_fp16.h>
#include <cstdint>

#define TT 2048
#define CC 1024
#define NH 16
#define BB 2
#define NHC (NH*CC)   // 16384

// ---- static device scratch (no allocation anywhere) ----
__device__ float  g_attn[(size_t)BB*NH*TT*TT];               // 512 MB fp32 scores
__device__ __align__(16) __half g_ph [(size_t)BB*NH*TT*TT];  // 256 MB fp16 P
__device__ __align__(16) __half g_oh [(size_t)BB*TT*NHC];    // 128 MB fp16 O
__device__ __align__(16) __half g_xh [(size_t)BB*TT*CC];     //   8 MB fp16 x
__device__ __align__(16) __half g_xTh[(size_t)BB*CC*TT];     //   8 MB fp16 x^T
__device__ __align__(16) __half g_wTh[(size_t)CC*NHC];       //  32 MB fp16 W^T

// ---------------------------------------------------------------------------
// helpers (family-wide PTX only: cp.async / ldmatrix / mma.sync)
// ---------------------------------------------------------------------------
__device__ __forceinline__ uint32_t smem_u32(const void* p){
    uint32_t a;
    asm("{ .reg .u64 t; cvta.to.shared.u64 t, %1; cvt.u32.u64 %0, t; }"
        : "=r"(a) : "l"(p));
    return a;
}
#define CPA(dst,src) \
    asm volatile("cp.async.cg.shared.global [%0], [%1], 16;" :: "r"(dst), "l"(src))
#define CPA_COMMIT() asm volatile("cp.async.commit_group;" ::: "memory")
#define CPA_WAIT(n)  asm volatile("cp.async.wait_group %0;" :: "n"(n) : "memory")

__device__ __forceinline__ void ldm_x4(uint32_t* r, uint32_t a){
    asm volatile("ldmatrix.sync.aligned.m8n8.x4.shared.b16 {%0,%1,%2,%3}, [%4];"
        : "=r"(r[0]), "=r"(r[1]), "=r"(r[2]), "=r"(r[3]) : "r"(a));
}
__device__ __forceinline__ void mma16(float* c, const uint32_t* a, const uint32_t* b){
    asm volatile("mma.sync.aligned.m16n8k16.row.col.f32.f16.f16.f32 "
        "{%0,%1,%2,%3}, {%4,%5,%6,%7}, {%8,%9}, {%0,%1,%2,%3};"
        : "+f"(c[0]), "+f"(c[1]), "+f"(c[2]), "+f"(c[3])
        : "r"(a[0]), "r"(a[1]), "r"(a[2]), "r"(a[3]), "r"(b[0]), "r"(b[1]));
}

// ---------------------------------------------------------------------------
// fp16 warp-MMA GEMM: CTA tile 128x128, BK=64, 3-stage cp.async pipeline.
// A: K-major [m][k] (lda elems).  Bt: K-major transposed-B [n][k] (ldb elems).
// MODE: 0 = fp32 store, 1 = fp16 store, 2 = fp32 scaled store.
// smem: 3 stages x (A 16KB + B 16KB) = 96KB; 128B rows, XOR-16B swizzle.
// ---------------------------------------------------------------------------
template<int MODE, typename CT>
__device__ __forceinline__ void gemm_h(
    const __half* __restrict__ A,  int lda,
    const __half* __restrict__ Bt, int ldb,
    CT* __restrict__ C, int ldc,
    int K, int m0, int n0, float scl)
{
    extern __shared__ char sm[];
    const uint32_t sb = smem_u32(sm);
    const int tid = threadIdx.x, lane = tid & 31, wid = tid >> 5;
    const int wm = (wid & 1) * 64;      // warp grid 2 (M) x 4 (N): 64x32 per warp
    const int wn = (wid >> 1) * 32;

    // gmem->smem: 32 rows/pass (4 passes), 8x16B chunks per 128B row (64 halves)
    const int lrow = tid >> 3;
    const uint32_t lcb = (tid & 7) * 16;
    const __half* aptr = A  + (size_t)(m0 + lrow) * lda + (tid & 7) * 8;
    const __half* bptr = Bt + (size_t)(n0 + lrow) * ldb + (tid & 7) * 8;

    auto load_stage = [&](int stg, int k0){
        const uint32_t base = sb + stg * 32768;
        #pragma unroll
        for (int i = 0; i < 4; i++){
            const int r = lrow + 32 * i;
            const uint32_t d = base + r * 128 + (lcb ^ ((r & 7) << 4));
            CPA(d,         aptr + (size_t)(32 * i) * lda + k0);
            CPA(d + 16384, bptr + (size_t)(32 * i) * ldb + k0);
        }
        CPA_COMMIT();
    };

    // ldmatrix lane geometry (m16n8k16 fragments)
    const int arow = ((lane >> 3) & 1) * 8 + (lane & 7);   // A: m-half x k-half
    const uint32_t acb = ((lane >> 4) & 1) * 16;
    const int bnr  = ((lane >> 4) & 1) * 8 + (lane & 7);   // B: n-half x k-half
    const uint32_t bcb = ((lane >> 3) & 1) * 16;
    const uint32_t ax = (lane & 7) << 4;                   // XOR term (row&7)

    const int S = K >> 6;
    load_stage(0, 0);
    if (S > 1) load_stage(1, 64);

    float acc[4][4][4] = {};

    for (int s = 0; s < S; s++){
        if (s + 2 <= S) { CPA_WAIT(1); } else { CPA_WAIT(0); }
        __syncthreads();
        if (s + 2 < S) load_stage((s + 2) % 3, (s + 2) << 6);

        const uint32_t base = sb + (s % 3) * 32768;
        #pragma unroll
        for (int c = 0; c < 4; c++){               // 4 k-steps of 16 within BK=64
            uint32_t af[4][4], bf[2][4];
            #pragma unroll
            for (int mf = 0; mf < 4; mf++)
                ldm_x4(af[mf], base + (wm + mf*16 + arow) * 128
                                    + ((c*32 + acb) ^ ax));
            #pragma unroll
            for (int p = 0; p < 2; p++)
                ldm_x4(bf[p], base + 16384 + (wn + p*16 + bnr) * 128
                                    + ((c*32 + bcb) ^ ax));
            #pragma unroll
            for (int mf = 0; mf < 4; mf++)
                #pragma unroll
                for (int nf = 0; nf < 4; nf++)
                    mma16(acc[mf][nf], af[mf], &bf[nf >> 1][(nf & 1) * 2]);
        }
    }

    // epilogue
    const int lr = lane >> 2, lc = (lane & 3) * 2;
    #pragma unroll
    for (int mf = 0; mf < 4; mf++){
        const int row = m0 + wm + mf * 16 + lr;
        #pragma unroll
        for (int nf = 0; nf < 4; nf++){
            const int col = n0 + wn + nf * 8 + lc;
            float v0 = acc[mf][nf][0], v1 = acc[mf][nf][1];
            float v2 = acc[mf][nf][2], v3 = acc[mf][nf][3];
            if (MODE == 2){ v0 *= scl; v1 *= scl; v2 *= scl; v3 *= scl; }
            if (MODE == 1){
                __half* Ch = (__half*)C;
                *(__half2*)&Ch[(size_t)row * ldc + col]       = __floats2half2_rn(v0, v1);
                *(__half2*)&Ch[(size_t)(row + 8) * ldc + col] = __floats2half2_rn(v2, v3);
            } else {
                float* Cf = (float*)C;
                *(float2*)&Cf[(size_t)row * ldc + col]       = make_float2(v0, v1);
                *(float2*)&Cf[(size_t)(row + 8) * ldc + col] = make_float2(v2, v3);
            }
        }
    }
}

// ---------------------------------------------------------------------------
// GEMM kernels
// ---------------------------------------------------------------------------
__global__ __launch_bounds__(256) void scores_mma(){
    const int bh = blockIdx.z, b = bh >> 4, h = bh & 15;
    const __half* Ax = g_xh + (size_t)b * TT * CC + h * 64;
    gemm_h<2>(Ax, CC, Ax, CC,
              g_attn + (size_t)bh * TT * TT, TT,
              64, blockIdx.y * 128, blockIdx.x * 128, 0.125f);
}

__global__ __launch_bounds__(256) void pv_mma(){
    const int bh = blockIdx.z, b = bh >> 4, h = bh & 15;
    gemm_h<1>(g_ph + (size_t)bh * TT * TT, TT,
              g_xTh + (size_t)b * CC * TT, TT,
              g_oh + (size_t)b * TT * NHC + h * CC, NHC,
              TT, blockIdx.y * 128, blockIdx.x * 128, 0.f);
}

__global__ __launch_bounds__(256) void proj_mma(float* __restrict__ out){
    gemm_h<0>(g_oh, NHC, g_wTh, NHC, out, CC,
              NHC, blockIdx.y * 128, blockIdx.x * 128, 0.f);
}

// ---------------------------------------------------------------------------
// Prep: x -> fp16 (g_xh) + fp16 transpose (g_xTh); W -> fp16 transpose (g_wTh)
// ---------------------------------------------------------------------------
__global__ __launch_bounds__(256) void prep_x(const float* __restrict__ x){
    __shared__ float t[32][33];
    const int b = blockIdx.z;
    const int t0 = blockIdx.x * 32, c0 = blockIdx.y * 32;
    const int tx = threadIdx.x & 31, ty = threadIdx.x >> 5;
    #pragma unroll
    for (int i = 0; i < 4; i++){
        const int row = ty + 8 * i;
        const size_t idx = (size_t)b * TT * CC + (size_t)(t0 + row) * CC + c0 + tx;
        const float v = x[idx];
        g_xh[idx] = __float2half_rn(v);
        t[row][tx] = v;
    }
    __syncthreads();
    #pragma unroll
    for (int i = 0; i < 4; i++){
        const int row = ty + 8 * i;   // c index within tile
        g_xTh[(size_t)b * CC * TT + (size_t)(c0 + row) * TT + t0 + tx] =
            __float2half_rn(t[tx][row]);
    }
}

__global__ __launch_bounds__(256) void prep_w(const float* __restrict__ w){
    __shared__ float t[32][33];
    const int k0 = blockIdx.x * 32, n0 = blockIdx.y * 32;
    const int tx = threadIdx.x & 31, ty = threadIdx.x >> 5;
    #pragma unroll
    for (int i = 0; i < 4; i++){
        const int row = ty + 8 * i;
        t[row][tx] = w[(size_t)(k0 + row) * CC + n0 + tx];
    }
    __syncthreads();
    #pragma unroll
    for (int i = 0; i < 4; i++){
        const int row = ty + 8 * i;   // n index within tile
        g_wTh[(size_t)(n0 + row) * NHC + k0 + tx] = __float2half_rn(t[tx][row]);
    }
}

// ---------------------------------------------------------------------------
// Softmax over last dim (2048): fp32 in (g_attn), fp16 out (g_ph).
// 256 threads/row, 8 contiguous elems per thread.
// ---------------------------------------------------------------------------
__global__ __launch_bounds__(256) void softmax_kernel(){
    const size_t r = blockIdx.x;
    const float* p = g_attn + r * TT;
    __half* q = g_ph + r * TT;
    const int tid = threadIdx.x;
    __shared__ float red[8];

    float v[8];
    *(float4*)&v[0] = *(const float4*)&p[tid * 8];
    *(float4*)&v[4] = *(const float4*)&p[tid * 8 + 4];

    float mx = v[0];
    #pragma unroll
    for (int i = 1; i < 8; i++) mx = fmaxf(mx, v[i]);
    #pragma unroll
    for (int o = 16; o; o >>= 1) mx = fmaxf(mx, __shfl_xor_sync(0xFFFFFFFFu, mx, o));
    if ((tid & 31) == 0) red[tid >> 5] = mx;
    __syncthreads();
    mx = red[0];
    #pragma unroll
    for (int i = 1; i < 8; i++) mx = fmaxf(mx, red[i]);
    __syncthreads();

    float sum = 0.f;
    #pragma unroll
    for (int i = 0; i < 8; i++){ v[i] = __expf(v[i] - mx); sum += v[i]; }
    #pragma unroll
    for (int o = 16; o; o >>= 1) sum += __shfl_xor_sync(0xFFFFFFFFu, sum, o);
    if ((tid & 31) == 0) red[tid >> 5] = sum;
    __syncthreads();
    sum = 0.f;
    #pragma unroll
    for (int i = 0; i < 8; i++) sum += red[i];
    const float inv = 1.0f / sum;

    __half2 h[4];
    #pragma unroll
    for (int j = 0; j < 4; j++)
        h[j] = __floats2half2_rn(v[2*j] * inv, v[2*j+1] * inv);
    *(uint4*)&q[tid * 8] = *(uint4*)h;
}

// ---------------------------------------------------------------------------
extern "C" void kernel_launch(void* const* d_in, const int* in_sizes, int n_in,
                              void* d_out, int out_size) {
    const float* x = (const float*)d_in[0];
    const float* w = (const float*)d_in[1];
    float* out = (float*)d_out;

    const int SMEM = 3 * 32768;   // 98304
    cudaFuncSetAttribute(scores_mma, cudaFuncAttributeMaxDynamicSharedMemorySize, SMEM);
    cudaFuncSetAttribute(pv_mma,     cudaFuncAttributeMaxDynamicSharedMemorySize, SMEM);
    cudaFuncSetAttribute(proj_mma,   cudaFuncAttributeMaxDynamicSharedMemorySize, SMEM);

    prep_x<<<dim3(TT/32, CC/32, BB), 256>>>(x);
    prep_w<<<dim3(NHC/32, CC/32), 256>>>(w);
    scores_mma<<<dim3(TT/128, TT/128, BB*NH), 256, SMEM>>>();
    softmax_kernel<<<BB*NH*TT, 256>>>();
    pv_mma<<<dim3(CC/128, TT/128, BB*NH), 256, SMEM>>>();
    proj_mma<<<dim3(CC/128, (BB*TT)/128), 256, SMEM>>>(out);
}